// round 2
// baseline (speedup 1.0000x reference)
#include <cuda_runtime.h>

#define Bq   64
#define NPG  501
#define NN   (Bq * NPG)        // 32064
#define HID  128
#define LMD  1024
#define NREL 42
#define EMAX 520001
#define NPAD (NN + 128)

// ---------------- scratch (device globals; no allocs) ----------------
__device__ int   g_is64;
__device__ int   g_src[EMAX];
__device__ int   g_dst[EMAX];
__device__ int   g_etype[EMAX];
__device__ int   g_ctxn[Bq];
__device__ float g_ctx[Bq * HID];
__device__ float g_tdot[NREL];
__device__ float g_tmpT[Bq * HID * HID];      // [b][h][k]
__device__ float g_x[NPAD * HID];
__device__ float g_nodes[NPAD * HID];
__device__ float g_xl[NPAD * HID];
__device__ float g_as[NPAD];
__device__ float g_ad[NPAD];
__device__ float g_loop[NN];
__device__ int   g_deg[NN];
__device__ int   g_off[NN + 1];
__device__ int   g_pos[NN];
__device__ int   g_csrc[EMAX];
__device__ float g_cae[EMAX];

// detect int64 vs int32 index buffers: ctx_nodes[0]=0, ctx_nodes[1]=501.
// int64 layout -> 32-bit word #1 is high word of element 0 == 0.
// int32 layout -> word #1 == 501.
__global__ void k_flag(const void* __restrict__ ctxn) {
    g_is64 = (((const int*)ctxn)[1] == 0) ? 1 : 0;
}

__global__ void k_cvt(const void* __restrict__ ei, const void* __restrict__ et,
                      const void* __restrict__ ctxn, int E) {
    int i = blockIdx.x * blockDim.x + threadIdx.x;
    bool is64 = (g_is64 != 0);
    if (i < E) {
        if (is64) {
            g_src[i]   = (int)((const long long*)ei)[i];
            g_dst[i]   = (int)((const long long*)ei)[E + i];
            g_etype[i] = (int)((const long long*)et)[i];
        } else {
            g_src[i]   = ((const int*)ei)[i];
            g_dst[i]   = ((const int*)ei)[E + i];
            g_etype[i] = ((const int*)et)[i];
        }
    }
    if (i < Bq)
        g_ctxn[i] = is64 ? (int)((const long long*)ctxn)[i] : ((const int*)ctxn)[i];
}

// ---------------- v_edge = W_edge@att_edge; table_dot ----------------
__global__ void k_prep(const float* __restrict__ We, const float* __restrict__ ae,
                       const float* __restrict__ tab) {
    __shared__ float sv[HID];
    int t = threadIdx.x;
    float acc = 0.f;
    for (int j = 0; j < HID; j++) acc += We[t * HID + j] * ae[j];
    sv[t] = acc;
    __syncthreads();
    if (t < NREL) {
        float a2 = 0.f;
        for (int j = 0; j < HID; j++) a2 += tab[t * HID + j] * sv[j];
        g_tdot[t] = a2;
    }
}

// ctx_emb = lm @ W_lm + b_lm
__global__ void k_ctx(const float* __restrict__ lm, const float* __restrict__ W,
                      const float* __restrict__ bl) {
    int b = blockIdx.x, c = threadIdx.x;
    const float* l0 = lm + b * LMD;
    float acc = bl[c];
    for (int l = 0; l < LMD; l++) acc += l0[l] * W[l * HID + c];
    g_ctx[b * HID + c] = acc;
}

// copy node_emb -> g_x, zero deg
__global__ void k_init(const float* __restrict__ ne) {
    int i = blockIdx.x * blockDim.x + threadIdx.x;
    int stride = gridDim.x * blockDim.x;
    for (int j = i; j < NN * HID; j += stride) g_x[j] = ne[j];
    for (int j = i; j < NN; j += stride) g_deg[j] = 0;
}

__global__ void k_setctx() {
    int b = blockIdx.x, c = threadIdx.x;
    int n = g_ctxn[b];
    g_x[(size_t)n * HID + c] = g_ctx[b * HID + c];
}

__global__ void k_deg(int E) {
    int i = blockIdx.x * blockDim.x + threadIdx.x;
    if (i < E) atomicAdd(&g_deg[g_dst[i]], 1);
}

// single-block exclusive scan over g_deg -> g_off, g_pos
__global__ void k_scan() {
    __shared__ int sp[1024];
    int t = threadIdx.x;
    int base = t * 32;
    int loc[32];
    int s = 0;
#pragma unroll
    for (int i = 0; i < 32; i++) {
        int idx = base + i;
        int v = (idx < NN) ? g_deg[idx] : 0;
        loc[i] = s;
        s += v;
    }
    sp[t] = s;
    __syncthreads();
    for (int d = 1; d < 1024; d <<= 1) {
        int v = (t >= d) ? sp[t - d] : 0;
        __syncthreads();
        sp[t] += v;
        __syncthreads();
    }
    int chunk = (t == 0) ? 0 : sp[t - 1];
#pragma unroll
    for (int i = 0; i < 32; i++) {
        int idx = base + i;
        if (idx < NN) {
            int o = chunk + loc[i];
            g_off[idx] = o;
            g_pos[idx] = o;
        }
    }
    if (t == 1023) g_off[NN] = sp[1023];
}

__global__ void k_fill(int E) {
    int i = blockIdx.x * blockDim.x + threadIdx.x;
    if (i < E) {
        int d = g_dst[i];
        int p = atomicAdd(&g_pos[d], 1);
        g_csrc[p] = g_src[i];
        g_cae[p] = g_tdot[g_etype[i]];
    }
}

// self-loop attention bias = mean of incoming table_dot
__global__ void k_loopdot() {
    int w = (blockIdx.x * blockDim.x + threadIdx.x) >> 5;
    int lane = threadIdx.x & 31;
    if (w >= NN) return;
    int s = g_off[w], e = g_off[w + 1];
    float acc = 0.f;
    for (int i = s + lane; i < e; i += 32) acc += g_cae[i];
    for (int o = 16; o; o >>= 1) acc += __shfl_xor_sync(0xffffffffu, acc, o);
    if (lane == 0) {
        int d = e - s;
        g_loop[w] = d ? acc / (float)d : 0.f;
    }
}

// tmpT[b][h][k] = sum_l lm[b,l]*W_bil[k,l,h]  — one block per k
__global__ void __launch_bounds__(256) k_tmp(const float* __restrict__ lm,
                                             const float* __restrict__ Wb) {
    int k = blockIdx.x;
    int t = threadIdx.x;
    int bg = t >> 4, hg = t & 15;
    int b0 = bg * 4, h0 = hg * 8;
    const float* Wk = Wb + (size_t)k * LMD * HID;
    float acc[4][8];
#pragma unroll
    for (int i = 0; i < 4; i++)
#pragma unroll
        for (int j = 0; j < 8; j++) acc[i][j] = 0.f;

    for (int l = 0; l < LMD; l += 4) {
        float a[4][4];
#pragma unroll
        for (int i = 0; i < 4; i++) {
            float4 v = *(const float4*)&lm[(size_t)(b0 + i) * LMD + l];
            a[i][0] = v.x; a[i][1] = v.y; a[i][2] = v.z; a[i][3] = v.w;
        }
#pragma unroll
        for (int u = 0; u < 4; u++) {
            float4 w0 = *(const float4*)&Wk[(size_t)(l + u) * HID + h0];
            float4 w1 = *(const float4*)&Wk[(size_t)(l + u) * HID + h0 + 4];
            float wr[8] = {w0.x, w0.y, w0.z, w0.w, w1.x, w1.y, w1.z, w1.w};
#pragma unroll
            for (int i = 0; i < 4; i++) {
                float av = a[i][u];
#pragma unroll
                for (int j = 0; j < 8; j++) acc[i][j] += av * wr[j];
            }
        }
    }
#pragma unroll
    for (int i = 0; i < 4; i++)
#pragma unroll
        for (int j = 0; j < 8; j++)
            g_tmpT[(size_t)(b0 + i) * HID * HID + (size_t)(h0 + j) * HID + k] = acc[i][j];
}

// C[m,k] = sum_h A[m,h]*B[h,k] (+bias); optional fused row-dots with att_src/att_dst
// mode 0: A=g_x(+b*sA), B=g_tmpT[b], C=g_nodes(+b*sA)   (nodes0)
// mode 1: A=g_nodes, B=Bext(W_gat), C=g_xl, writes g_as/g_ad
__global__ void __launch_bounds__(256) k_gemm(int mode, const float* __restrict__ Bext,
                                              int M, int sA,
                                              const float* __restrict__ bias,
                                              const float* __restrict__ atts,
                                              const float* __restrict__ attd) {
    const float* A = mode ? g_nodes : g_x;
    float* C = mode ? g_xl : g_nodes;
    const float* Bm = mode ? Bext : (g_tmpT + (size_t)blockIdx.y * HID * HID);
    A += (size_t)blockIdx.y * sA;
    C += (size_t)blockIdx.y * sA;

    int t = threadIdx.x;
    int rg = t >> 3, cg = t & 7;
    int m0 = blockIdx.x * 128 + rg * 4;
    int k0 = cg * 16;

    float acc[4][16];
#pragma unroll
    for (int i = 0; i < 4; i++)
#pragma unroll
        for (int j = 0; j < 16; j++) acc[i][j] = 0.f;

    for (int h = 0; h < HID; h += 4) {
        float a[4][4];
#pragma unroll
        for (int i = 0; i < 4; i++) {
            float4 v = *(const float4*)&A[(size_t)(m0 + i) * HID + h];
            a[i][0] = v.x; a[i][1] = v.y; a[i][2] = v.z; a[i][3] = v.w;
        }
#pragma unroll
        for (int u = 0; u < 4; u++) {
            float br[16];
#pragma unroll
            for (int q = 0; q < 4; q++) {
                float4 w = *(const float4*)&Bm[(size_t)(h + u) * HID + k0 + q * 4];
                br[q * 4 + 0] = w.x; br[q * 4 + 1] = w.y;
                br[q * 4 + 2] = w.z; br[q * 4 + 3] = w.w;
            }
#pragma unroll
            for (int i = 0; i < 4; i++) {
                float av = a[i][u];
#pragma unroll
                for (int j = 0; j < 16; j++) acc[i][j] += av * br[j];
            }
        }
    }

    float bs[16];
    if (bias) {
#pragma unroll
        for (int q = 0; q < 4; q++) {
            float4 w = *(const float4*)&bias[k0 + q * 4];
            bs[q * 4 + 0] = w.x; bs[q * 4 + 1] = w.y;
            bs[q * 4 + 2] = w.z; bs[q * 4 + 3] = w.w;
        }
    } else {
#pragma unroll
        for (int j = 0; j < 16; j++) bs[j] = 0.f;
    }

#pragma unroll
    for (int i = 0; i < 4; i++) {
        int m = m0 + i;
        if (m < M) {
#pragma unroll
            for (int q = 0; q < 4; q++) {
                float4 w;
                w.x = acc[i][q * 4 + 0] + bs[q * 4 + 0];
                w.y = acc[i][q * 4 + 1] + bs[q * 4 + 1];
                w.z = acc[i][q * 4 + 2] + bs[q * 4 + 2];
                w.w = acc[i][q * 4 + 3] + bs[q * 4 + 3];
                *(float4*)&C[(size_t)m * HID + k0 + q * 4] = w;
            }
        }
    }

    if (atts) {
        float sa[16], da[16];
#pragma unroll
        for (int q = 0; q < 4; q++) {
            float4 w = *(const float4*)&atts[k0 + q * 4];
            sa[q * 4] = w.x; sa[q * 4 + 1] = w.y; sa[q * 4 + 2] = w.z; sa[q * 4 + 3] = w.w;
            float4 u = *(const float4*)&attd[k0 + q * 4];
            da[q * 4] = u.x; da[q * 4 + 1] = u.y; da[q * 4 + 2] = u.z; da[q * 4 + 3] = u.w;
        }
#pragma unroll
        for (int i = 0; i < 4; i++) {
            float ps = 0.f, pd = 0.f;
#pragma unroll
            for (int j = 0; j < 16; j++) {
                ps += acc[i][j] * sa[j];
                pd += acc[i][j] * da[j];
            }
            for (int o = 4; o; o >>= 1) {
                ps += __shfl_down_sync(0xffffffffu, ps, o, 8);
                pd += __shfl_down_sync(0xffffffffu, pd, o, 8);
            }
            int m = m0 + i;
            if (cg == 0 && m < M) { g_as[m] = ps; g_ad[m] = pd; }
        }
    }
}

// one warp per dst node: softmax over incoming edges (+self loop), weighted aggregate
__global__ void k_hop(const float* __restrict__ gbias) {
    int w = (blockIdx.x * blockDim.x + threadIdx.x) >> 5;
    int lane = threadIdx.x & 31;
    if (w >= NN) return;
    int s = g_off[w], e = g_off[w + 1];
    float adn = g_ad[w];
    float aself = g_as[w] + adn + g_loop[w];
    aself = aself >= 0.f ? aself : 0.2f * aself;
    float m = aself;
    for (int i = s + lane; i < e; i += 32) {
        float a = g_as[g_csrc[i]] + adn + g_cae[i];
        a = a >= 0.f ? a : 0.2f * a;
        m = fmaxf(m, a);
    }
    for (int o = 16; o; o >>= 1) m = fmaxf(m, __shfl_xor_sync(0xffffffffu, m, o));

    float eself = __expf(aself - m);
    float s_sum = eself;
    float4 v = ((const float4*)&g_xl[(size_t)w * HID])[lane];
    float4 acc;
    acc.x = eself * v.x; acc.y = eself * v.y; acc.z = eself * v.z; acc.w = eself * v.w;

    for (int i = s; i < e; i++) {
        int src = g_csrc[i];
        float a = g_as[src] + adn + g_cae[i];
        a = a >= 0.f ? a : 0.2f * a;
        float ee = __expf(a - m);
        s_sum += ee;
        float4 u = ((const float4*)&g_xl[(size_t)src * HID])[lane];
        acc.x += ee * u.x; acc.y += ee * u.y; acc.z += ee * u.z; acc.w += ee * u.w;
    }
    float inv = 1.f / s_sum;
    float4 bb = ((const float4*)gbias)[lane];
    float4 o;
    o.x = acc.x * inv + bb.x; o.y = acc.y * inv + bb.y;
    o.z = acc.z * inv + bb.z; o.w = acc.w * inv + bb.w;
    ((float4*)&g_nodes[(size_t)w * HID])[lane] = o;
}

__global__ void k_out(float* __restrict__ out) {
    int b = blockIdx.x, c = threadIdx.x;
    int n = g_ctxn[b];
    out[b * HID + c] = g_nodes[(size_t)n * HID + c];
}

extern "C" void kernel_launch(void* const* d_in, const int* in_sizes, int n_in,
                              void* d_out, int out_size) {
    const float* lm    = (const float*)d_in[0];
    const float* ne    = (const float*)d_in[1];
    const void*  ei    = d_in[2];
    const void*  et    = d_in[3];
    const void*  ctxn  = d_in[4];
    const float* Wlm  = (const float*)d_in[5];
    const float* blm  = (const float*)d_in[6];
    const float* Wbil = (const float*)d_in[7];
    const float* bbil = (const float*)d_in[8];
    const float* tab  = (const float*)d_in[9];
    const float* Wgat = (const float*)d_in[10];
    const float* atts = (const float*)d_in[11];
    const float* attd = (const float*)d_in[12];
    const float* Wed  = (const float*)d_in[13];
    const float* atte = (const float*)d_in[14];
    const float* gb   = (const float*)d_in[15];
    float* out = (float*)d_out;

    int E = in_sizes[2] / 2;
    int eb = (E + 255) / 256;

    k_flag<<<1, 1>>>(ctxn);
    k_cvt<<<eb, 256>>>(ei, et, ctxn, E);
    k_prep<<<1, 128>>>(Wed, atte, tab);
    k_ctx<<<Bq, 128>>>(lm, Wlm, blm);
    k_init<<<1024, 256>>>(ne);
    k_setctx<<<Bq, 128>>>();
    k_deg<<<eb, 256>>>(E);
    k_scan<<<1, 1024>>>();
    k_fill<<<eb, 256>>>(E);
    k_loopdot<<<(NN + 7) / 8, 256>>>();
    k_tmp<<<HID, 256>>>(lm, Wbil);

    // nodes0: per-graph  xg @ tmp[b]^T + b_bil
    dim3 g0((NPG + 127) / 128, Bq);
    k_gemm<<<g0, 256>>>(0, nullptr, NPG, NPG * HID, bbil, nullptr, nullptr);

    for (int hop = 0; hop < 3; hop++) {
        dim3 g1((NN + 127) / 128, 1);
        k_gemm<<<g1, 256>>>(1, Wgat, NN, 0, nullptr, atts, attd);
        k_hop<<<(NN + 7) / 8, 256>>>(gb);
    }
    k_out<<<Bq, 128>>>(out);
}

// round 4
// speedup vs baseline: 1.2257x; 1.2257x over previous
#include <cuda_runtime.h>

#define Bq   64
#define NPG  501
#define NN   (Bq * NPG)        // 32064
#define HID  128
#define LMD  1024
#define NREL 42
#define EMAX 520001
#define NPAD (NN + 128)

// ---------------- scratch (device globals; no allocs) ----------------
__device__ int   g_is64;
__device__ int   g_src[EMAX];
__device__ int   g_dst[EMAX];
__device__ int   g_etype[EMAX];
__device__ int   g_ctxn[Bq];
__device__ float g_ctx[Bq * HID];
__device__ float g_tdot[NREL];
__device__ float g_tmpT[Bq * HID * HID];      // [b][h][k]
__device__ float g_x[NPAD * HID];
__device__ float g_nodes[NPAD * HID];
__device__ float g_xl[NPAD * HID];
__device__ float g_as[NPAD];
__device__ float g_ad[NPAD];
__device__ float g_loop[NN];
__device__ int   g_deg[NN];
__device__ int   g_off[NN + 1];
__device__ int   g_pos[NN];
__device__ int   g_csrc[EMAX];
__device__ float g_cae[EMAX];
// active-set pruning
__device__ int   g_isctx[NN];
__device__ int   g_m3[NN];
__device__ int   g_m2[NN];
__device__ int   g_list2[NN];
__device__ int   g_list3[NN];
__device__ int   g_cnt2;
__device__ int   g_cnt3;

// detect int64 vs int32 index buffers: ctx_nodes[0]=0, ctx_nodes[1]=501.
__global__ void k_flag(const void* __restrict__ ctxn) {
    g_is64 = (((const int*)ctxn)[1] == 0) ? 1 : 0;
}

__global__ void k_cvt(const void* __restrict__ ei, const void* __restrict__ et,
                      const void* __restrict__ ctxn, int E) {
    int i = blockIdx.x * blockDim.x + threadIdx.x;
    bool is64 = (g_is64 != 0);
    if (i < E) {
        if (is64) {
            g_src[i]   = (int)((const long long*)ei)[i];
            g_dst[i]   = (int)((const long long*)ei)[E + i];
            g_etype[i] = (int)((const long long*)et)[i];
        } else {
            g_src[i]   = ((const int*)ei)[i];
            g_dst[i]   = ((const int*)ei)[E + i];
            g_etype[i] = ((const int*)et)[i];
        }
    }
    if (i < Bq)
        g_ctxn[i] = is64 ? (int)((const long long*)ctxn)[i] : ((const int*)ctxn)[i];
}

// zero scratch + copy node_emb -> g_x
__global__ void k_init(const float* __restrict__ ne) {
    int i = blockIdx.x * blockDim.x + threadIdx.x;
    int stride = gridDim.x * blockDim.x;
    for (int j = i; j < NN * HID; j += stride) g_x[j] = ne[j];
    for (int j = i; j < NN; j += stride) {
        g_deg[j] = 0; g_isctx[j] = 0; g_m3[j] = 0; g_m2[j] = 0;
    }
    if (i == 0) { g_cnt2 = 0; g_cnt3 = 0; }
}

__global__ void k_isctx() {
    int b = threadIdx.x;
    int n = g_ctxn[b];
    g_isctx[n] = 1;
    g_m3[n] = 1;
}

__global__ void k_mark3(int E) {
    int i = blockIdx.x * blockDim.x + threadIdx.x;
    if (i < E && g_isctx[g_dst[i]]) g_m3[g_src[i]] = 1;
}

__global__ void k_mark2(int E) {
    int i = blockIdx.x * blockDim.x + threadIdx.x;
    if (i < E && g_m3[g_dst[i]]) g_m2[g_src[i]] = 1;
}

__global__ void k_compact() {
    int n = blockIdx.x * blockDim.x + threadIdx.x;
    if (n >= NN) return;
    int in3 = g_m3[n];
    int in2 = g_m2[n] | in3;
    if (in3) g_list3[atomicAdd(&g_cnt3, 1)] = n;
    if (in2) g_list2[atomicAdd(&g_cnt2, 1)] = n;
}

// ---------------- v_edge = W_edge@att_edge; table_dot ----------------
// MUST run before k_fill (k_fill consumes g_tdot).
__global__ void k_prep(const float* __restrict__ We, const float* __restrict__ ae,
                       const float* __restrict__ tab) {
    __shared__ float sv[HID];
    int t = threadIdx.x;
    float acc = 0.f;
    for (int j = 0; j < HID; j++) acc += We[t * HID + j] * ae[j];
    sv[t] = acc;
    __syncthreads();
    if (t < NREL) {
        float a2 = 0.f;
        for (int j = 0; j < HID; j++) a2 += tab[t * HID + j] * sv[j];
        g_tdot[t] = a2;
    }
}

// ctx_emb = lm @ W_lm + b_lm : grid 64, block 1024, 8-way L split
__global__ void __launch_bounds__(1024) k_ctx(const float* __restrict__ lm,
                                              const float* __restrict__ W,
                                              const float* __restrict__ bl) {
    __shared__ float red[1024];
    int b = blockIdx.x, t = threadIdx.x;
    int c = t & 127, lg = t >> 7;            // 8 chunks of 128 l
    const float* l0 = lm + (size_t)b * LMD + lg * 128;
    const float* Wp = W + (size_t)(lg * 128) * HID + c;
    float a0 = 0.f, a1 = 0.f;
#pragma unroll 8
    for (int l = 0; l < 128; l += 2) {
        a0 += l0[l] * Wp[(size_t)l * HID];
        a1 += l0[l + 1] * Wp[(size_t)(l + 1) * HID];
    }
    red[t] = a0 + a1;
    __syncthreads();
    for (int s = 512; s >= 128; s >>= 1) {
        if (t < s) red[t] += red[t + s];
        __syncthreads();
    }
    if (t < 128) g_ctx[b * HID + t] = red[t] + bl[t];
}

__global__ void k_setctx() {
    int b = blockIdx.x, c = threadIdx.x;
    int n = g_ctxn[b];
    g_x[(size_t)n * HID + c] = g_ctx[b * HID + c];
}

__global__ void k_deg(int E) {
    int i = blockIdx.x * blockDim.x + threadIdx.x;
    if (i < E) atomicAdd(&g_deg[g_dst[i]], 1);
}

// single-block exclusive scan over g_deg -> g_off, g_pos
__global__ void k_scan() {
    __shared__ int sp[1024];
    int t = threadIdx.x;
    int base = t * 32;
    int loc[32];
    int s = 0;
#pragma unroll
    for (int i = 0; i < 32; i++) {
        int idx = base + i;
        int v = (idx < NN) ? g_deg[idx] : 0;
        loc[i] = s;
        s += v;
    }
    sp[t] = s;
    __syncthreads();
    for (int d = 1; d < 1024; d <<= 1) {
        int v = (t >= d) ? sp[t - d] : 0;
        __syncthreads();
        sp[t] += v;
        __syncthreads();
    }
    int chunk = (t == 0) ? 0 : sp[t - 1];
#pragma unroll
    for (int i = 0; i < 32; i++) {
        int idx = base + i;
        if (idx < NN) {
            int o = chunk + loc[i];
            g_off[idx] = o;
            g_pos[idx] = o;
        }
    }
    if (t == 1023) g_off[NN] = sp[1023];
}

__global__ void k_fill(int E) {
    int i = blockIdx.x * blockDim.x + threadIdx.x;
    if (i < E) {
        int d = g_dst[i];
        int p = atomicAdd(&g_pos[d], 1);
        g_csrc[p] = g_src[i];
        g_cae[p] = g_tdot[g_etype[i]];
    }
}

// self-loop attention bias = mean of incoming table_dot
__global__ void k_loopdot() {
    int w = (blockIdx.x * blockDim.x + threadIdx.x) >> 5;
    int lane = threadIdx.x & 31;
    if (w >= NN) return;
    int s = g_off[w], e = g_off[w + 1];
    float acc = 0.f;
    for (int i = s + lane; i < e; i += 32) acc += g_cae[i];
    for (int o = 16; o; o >>= 1) acc += __shfl_xor_sync(0xffffffffu, acc, o);
    if (lane == 0) {
        int d = e - s;
        g_loop[w] = d ? acc / (float)d : 0.f;
    }
}

// tmpT[b][h][k] = sum_l lm[b,l]*W_bil[k,l,h]  — one block per k
__global__ void __launch_bounds__(256) k_tmp(const float* __restrict__ lm,
                                             const float* __restrict__ Wb) {
    int k = blockIdx.x;
    int t = threadIdx.x;
    int bg = t >> 4, hg = t & 15;
    int b0 = bg * 4, h0 = hg * 8;
    const float* Wk = Wb + (size_t)k * LMD * HID;
    float acc[4][8];
#pragma unroll
    for (int i = 0; i < 4; i++)
#pragma unroll
        for (int j = 0; j < 8; j++) acc[i][j] = 0.f;

    for (int l = 0; l < LMD; l += 4) {
        float a[4][4];
#pragma unroll
        for (int i = 0; i < 4; i++) {
            float4 v = *(const float4*)&lm[(size_t)(b0 + i) * LMD + l];
            a[i][0] = v.x; a[i][1] = v.y; a[i][2] = v.z; a[i][3] = v.w;
        }
#pragma unroll
        for (int u = 0; u < 4; u++) {
            float4 w0 = *(const float4*)&Wk[(size_t)(l + u) * HID + h0];
            float4 w1 = *(const float4*)&Wk[(size_t)(l + u) * HID + h0 + 4];
            float wr[8] = {w0.x, w0.y, w0.z, w0.w, w1.x, w1.y, w1.z, w1.w};
#pragma unroll
            for (int i = 0; i < 4; i++) {
                float av = a[i][u];
#pragma unroll
                for (int j = 0; j < 8; j++) acc[i][j] += av * wr[j];
            }
        }
    }
#pragma unroll
    for (int i = 0; i < 4; i++)
#pragma unroll
        for (int j = 0; j < 8; j++)
            g_tmpT[(size_t)(b0 + i) * HID * HID + (size_t)(h0 + j) * HID + k] = acc[i][j];
}

// full GEMM: mode 0: nodes0 per-graph; mode 1: xl = nodes@W_gat (+att dots)
__global__ void __launch_bounds__(256) k_gemm(int mode, const float* __restrict__ Bext,
                                              int M, int sA,
                                              const float* __restrict__ bias,
                                              const float* __restrict__ atts,
                                              const float* __restrict__ attd) {
    const float* A = mode ? g_nodes : g_x;
    float* C = mode ? g_xl : g_nodes;
    const float* Bm = mode ? Bext : (g_tmpT + (size_t)blockIdx.y * HID * HID);
    A += (size_t)blockIdx.y * sA;
    C += (size_t)blockIdx.y * sA;

    int t = threadIdx.x;
    int rg = t >> 3, cg = t & 7;
    int m0 = blockIdx.x * 128 + rg * 4;
    int k0 = cg * 16;

    float acc[4][16];
#pragma unroll
    for (int i = 0; i < 4; i++)
#pragma unroll
        for (int j = 0; j < 16; j++) acc[i][j] = 0.f;

    for (int h = 0; h < HID; h += 4) {
        float a[4][4];
#pragma unroll
        for (int i = 0; i < 4; i++) {
            float4 v = *(const float4*)&A[(size_t)(m0 + i) * HID + h];
            a[i][0] = v.x; a[i][1] = v.y; a[i][2] = v.z; a[i][3] = v.w;
        }
#pragma unroll
        for (int u = 0; u < 4; u++) {
            float br[16];
#pragma unroll
            for (int q = 0; q < 4; q++) {
                float4 w = *(const float4*)&Bm[(size_t)(h + u) * HID + k0 + q * 4];
                br[q * 4 + 0] = w.x; br[q * 4 + 1] = w.y;
                br[q * 4 + 2] = w.z; br[q * 4 + 3] = w.w;
            }
#pragma unroll
            for (int i = 0; i < 4; i++) {
                float av = a[i][u];
#pragma unroll
                for (int j = 0; j < 16; j++) acc[i][j] += av * br[j];
            }
        }
    }

    float bs[16];
    if (bias) {
#pragma unroll
        for (int q = 0; q < 4; q++) {
            float4 w = *(const float4*)&bias[k0 + q * 4];
            bs[q * 4 + 0] = w.x; bs[q * 4 + 1] = w.y;
            bs[q * 4 + 2] = w.z; bs[q * 4 + 3] = w.w;
        }
    } else {
#pragma unroll
        for (int j = 0; j < 16; j++) bs[j] = 0.f;
    }

#pragma unroll
    for (int i = 0; i < 4; i++) {
        int m = m0 + i;
        if (m < M) {
#pragma unroll
            for (int q = 0; q < 4; q++) {
                float4 w;
                w.x = acc[i][q * 4 + 0] + bs[q * 4 + 0];
                w.y = acc[i][q * 4 + 1] + bs[q * 4 + 1];
                w.z = acc[i][q * 4 + 2] + bs[q * 4 + 2];
                w.w = acc[i][q * 4 + 3] + bs[q * 4 + 3];
                *(float4*)&C[(size_t)m * HID + k0 + q * 4] = w;
            }
        }
    }

    if (atts) {
        float sa[16], da[16];
#pragma unroll
        for (int q = 0; q < 4; q++) {
            float4 w = *(const float4*)&atts[k0 + q * 4];
            sa[q * 4] = w.x; sa[q * 4 + 1] = w.y; sa[q * 4 + 2] = w.z; sa[q * 4 + 3] = w.w;
            float4 u = *(const float4*)&attd[k0 + q * 4];
            da[q * 4] = u.x; da[q * 4 + 1] = u.y; da[q * 4 + 2] = u.z; da[q * 4 + 3] = u.w;
        }
#pragma unroll
        for (int i = 0; i < 4; i++) {
            float ps = 0.f, pd = 0.f;
#pragma unroll
            for (int j = 0; j < 16; j++) {
                ps += acc[i][j] * sa[j];
                pd += acc[i][j] * da[j];
            }
            for (int o = 4; o; o >>= 1) {
                ps += __shfl_down_sync(0xffffffffu, ps, o, 8);
                pd += __shfl_down_sync(0xffffffffu, pd, o, 8);
            }
            int m = m0 + i;
            if (cg == 0 && m < M) { g_as[m] = ps; g_ad[m] = pd; }
        }
    }
}

// list-indirected GEMM: rows gathered from g_list2 (lsel=0) or g_list3 (lsel=1)
__global__ void __launch_bounds__(256) k_gemml(int lsel, const float* __restrict__ Bm,
                                               const float* __restrict__ atts,
                                               const float* __restrict__ attd) {
    int cnt = lsel ? g_cnt3 : g_cnt2;
    if (blockIdx.x * 128 >= cnt) return;
    const int* list = lsel ? g_list3 : g_list2;

    int t = threadIdx.x;
    int rg = t >> 3, cg = t & 7;
    int m0 = blockIdx.x * 128 + rg * 4;
    int k0 = cg * 16;

    int row[4];
    bool ok[4];
#pragma unroll
    for (int i = 0; i < 4; i++) {
        ok[i] = (m0 + i) < cnt;
        row[i] = ok[i] ? list[m0 + i] : list[0];
    }

    float acc[4][16];
#pragma unroll
    for (int i = 0; i < 4; i++)
#pragma unroll
        for (int j = 0; j < 16; j++) acc[i][j] = 0.f;

    for (int h = 0; h < HID; h += 4) {
        float a[4][4];
#pragma unroll
        for (int i = 0; i < 4; i++) {
            float4 v = *(const float4*)&g_nodes[(size_t)row[i] * HID + h];
            a[i][0] = v.x; a[i][1] = v.y; a[i][2] = v.z; a[i][3] = v.w;
        }
#pragma unroll
        for (int u = 0; u < 4; u++) {
            float br[16];
#pragma unroll
            for (int q = 0; q < 4; q++) {
                float4 w = *(const float4*)&Bm[(size_t)(h + u) * HID + k0 + q * 4];
                br[q * 4 + 0] = w.x; br[q * 4 + 1] = w.y;
                br[q * 4 + 2] = w.z; br[q * 4 + 3] = w.w;
            }
#pragma unroll
            for (int i = 0; i < 4; i++) {
                float av = a[i][u];
#pragma unroll
                for (int j = 0; j < 16; j++) acc[i][j] += av * br[j];
            }
        }
    }

#pragma unroll
    for (int i = 0; i < 4; i++) {
        if (ok[i]) {
#pragma unroll
            for (int q = 0; q < 4; q++) {
                float4 w;
                w.x = acc[i][q * 4 + 0]; w.y = acc[i][q * 4 + 1];
                w.z = acc[i][q * 4 + 2]; w.w = acc[i][q * 4 + 3];
                *(float4*)&g_xl[(size_t)row[i] * HID + k0 + q * 4] = w;
            }
        }
    }

    float sa[16], da[16];
#pragma unroll
    for (int q = 0; q < 4; q++) {
        float4 w = *(const float4*)&atts[k0 + q * 4];
        sa[q * 4] = w.x; sa[q * 4 + 1] = w.y; sa[q * 4 + 2] = w.z; sa[q * 4 + 3] = w.w;
        float4 u = *(const float4*)&attd[k0 + q * 4];
        da[q * 4] = u.x; da[q * 4 + 1] = u.y; da[q * 4 + 2] = u.z; da[q * 4 + 3] = u.w;
    }
#pragma unroll
    for (int i = 0; i < 4; i++) {
        float ps = 0.f, pd = 0.f;
#pragma unroll
        for (int j = 0; j < 16; j++) {
            ps += acc[i][j] * sa[j];
            pd += acc[i][j] * da[j];
        }
        for (int o = 4; o; o >>= 1) {
            ps += __shfl_down_sync(0xffffffffu, ps, o, 8);
            pd += __shfl_down_sync(0xffffffffu, pd, o, 8);
        }
        if (cg == 0 && ok[i]) { g_as[row[i]] = ps; g_ad[row[i]] = pd; }
    }
}

// restricted softmax-aggregation: dst nodes from a list (0=list2, 1=list3, 2=ctx)
__global__ void k_hopl(int lsel, const float* __restrict__ gbias) {
    int wi = (blockIdx.x * blockDim.x + threadIdx.x) >> 5;
    int lane = threadIdx.x & 31;
    int cnt = (lsel == 0) ? g_cnt2 : (lsel == 1) ? g_cnt3 : Bq;
    if (wi >= cnt) return;
    int w = (lsel == 0) ? g_list2[wi] : (lsel == 1) ? g_list3[wi] : g_ctxn[wi];

    int s = g_off[w], e = g_off[w + 1];
    float adn = g_ad[w];
    float aself = g_as[w] + adn + g_loop[w];
    aself = aself >= 0.f ? aself : 0.2f * aself;
    float m = aself;
    for (int i = s + lane; i < e; i += 32) {
        float a = g_as[g_csrc[i]] + adn + g_cae[i];
        a = a >= 0.f ? a : 0.2f * a;
        m = fmaxf(m, a);
    }
    for (int o = 16; o; o >>= 1) m = fmaxf(m, __shfl_xor_sync(0xffffffffu, m, o));

    float eself = __expf(aself - m);
    float s_sum = eself;
    float4 v = ((const float4*)&g_xl[(size_t)w * HID])[lane];
    float4 acc;
    acc.x = eself * v.x; acc.y = eself * v.y; acc.z = eself * v.z; acc.w = eself * v.w;

    for (int i = s; i < e; i++) {
        int src = g_csrc[i];
        float a = g_as[src] + adn + g_cae[i];
        a = a >= 0.f ? a : 0.2f * a;
        float ee = __expf(a - m);
        s_sum += ee;
        float4 u = ((const float4*)&g_xl[(size_t)src * HID])[lane];
        acc.x += ee * u.x; acc.y += ee * u.y; acc.z += ee * u.z; acc.w += ee * u.w;
    }
    float inv = 1.f / s_sum;
    float4 bb = ((const float4*)gbias)[lane];
    float4 o;
    o.x = acc.x * inv + bb.x; o.y = acc.y * inv + bb.y;
    o.z = acc.z * inv + bb.z; o.w = acc.w * inv + bb.w;
    ((float4*)&g_nodes[(size_t)w * HID])[lane] = o;
}

__global__ void k_out(float* __restrict__ out) {
    int b = blockIdx.x, c = threadIdx.x;
    int n = g_ctxn[b];
    out[b * HID + c] = g_nodes[(size_t)n * HID + c];
}

extern "C" void kernel_launch(void* const* d_in, const int* in_sizes, int n_in,
                              void* d_out, int out_size) {
    const float* lm    = (const float*)d_in[0];
    const float* ne    = (const float*)d_in[1];
    const void*  ei    = d_in[2];
    const void*  et    = d_in[3];
    const void*  ctxn  = d_in[4];
    const float* Wlm  = (const float*)d_in[5];
    const float* blm  = (const float*)d_in[6];
    const float* Wbil = (const float*)d_in[7];
    const float* bbil = (const float*)d_in[8];
    const float* tab  = (const float*)d_in[9];
    const float* Wgat = (const float*)d_in[10];
    const float* atts = (const float*)d_in[11];
    const float* attd = (const float*)d_in[12];
    const float* Wed  = (const float*)d_in[13];
    const float* atte = (const float*)d_in[14];
    const float* gb   = (const float*)d_in[15];
    float* out = (float*)d_out;

    int E = in_sizes[2] / 2;
    int eb = (E + 255) / 256;
    int nb128 = (NN + 127) / 128;      // GEMM row blocks
    int wb = (NN + 7) / 8;             // warp-per-node blocks (256 thr = 8 warps)

    k_flag<<<1, 1>>>(ctxn);
    k_cvt<<<eb, 256>>>(ei, et, ctxn, E);
    k_init<<<1024, 256>>>(ne);
    k_isctx<<<1, Bq>>>();
    k_mark3<<<eb, 256>>>(E);
    k_mark2<<<eb, 256>>>(E);
    k_compact<<<(NN + 255) / 256, 256>>>();

    k_prep<<<1, 128>>>(Wed, atte, tab);   // BEFORE k_fill: k_fill consumes g_tdot
    k_deg<<<eb, 256>>>(E);
    k_scan<<<1, 1024>>>();
    k_fill<<<eb, 256>>>(E);
    k_loopdot<<<wb, 256>>>();

    k_ctx<<<Bq, 1024>>>(lm, Wlm, blm);
    k_setctx<<<Bq, 128>>>();
    k_tmp<<<HID, 256>>>(lm, Wbil);

    // nodes0: per-graph  xg @ tmp[b]^T + b_bil
    dim3 g0((NPG + 127) / 128, Bq);
    k_gemm<<<g0, 256>>>(0, nullptr, NPG, NPG * HID, bbil, nullptr, nullptr);

    // hop 1: full GEMM (a_src needed everywhere), aggregate only at A2
    k_gemm<<<dim3(nb128, 1), 256>>>(1, Wgat, NN, 0, nullptr, atts, attd);
    k_hopl<<<wb, 256>>>(0, gb);

    // hop 2: GEMM over A2, aggregate at A3
    k_gemml<<<nb128, 256>>>(0, Wgat, atts, attd);
    k_hopl<<<wb, 256>>>(1, gb);

    // hop 3: GEMM over A3, aggregate at ctx
    k_gemml<<<nb128, 256>>>(1, Wgat, atts, attd);
    k_hopl<<<(Bq + 7) / 8, 256>>>(2, gb);

    k_out<<<Bq, 128>>>(out);
}